// round 1
// baseline (speedup 1.0000x reference)
#include <cuda_runtime.h>
#include <math.h>

#define DIM 1024
#define ROWS_PER_BLOCK 8
#define NTHREADS 256

// Integer LayerNorm, one warp per row (D=1024), single pass over x.
// sum_sq of centered values computed via sum_sq_x - 2*mean*sum_x + D*mean^2 (exact).
__global__ __launch_bounds__(NTHREADS)
void iln_kernel(const float* __restrict__ x,
                const float* __restrict__ weight,
                const float* __restrict__ bias,
                float* __restrict__ out,
                int n_rows)
{
    __shared__ int s_w[DIM];
    __shared__ int s_b[DIM];
    __shared__ int s_lut[32];

    const int tid = threadIdx.x;

    // Recompute the 32-entry isqrt LUT exactly (double): round((1<<15)/sqrt(2^parity*(1+m/16)))
    if (tid < 32) {
        const int parity = tid >> 4;
        const int mant = tid & 15;
        const double val = (double)(1 << parity) * (1.0 + (double)mant * 0.0625);
        s_lut[tid] = (int)llrint(32768.0 / sqrt(val));
    }
    // Quantize weight/bias once per block: round-half-even matches jnp.round
    for (int i = tid; i < DIM; i += NTHREADS) {
        s_w[i] = __float2int_rn(weight[i] * 256.0f);
        s_b[i] = __float2int_rn(bias[i] * 256.0f);
    }
    __syncthreads();

    const int warp = tid >> 5;
    const int lane = tid & 31;
    const int row = blockIdx.x * ROWS_PER_BLOCK + warp;
    if (row >= n_rows) return;

    const float4* __restrict__ xr = (const float4*)(x + (size_t)row * DIM);
    float4* __restrict__ orow = (float4*)(out + (size_t)row * DIM);

    // Load full row: 8 x float4 per lane, front-batched for MLP
    float4 v[8];
    #pragma unroll
    for (int j = 0; j < 8; j++) {
        v[j] = xr[j * 32 + lane];
    }

    int4 xi[8];
    int sum = 0;
    long long sumsq = 0;
    #pragma unroll
    for (int j = 0; j < 8; j++) {
        const int a = __float2int_rn(v[j].x);
        const int b = __float2int_rn(v[j].y);
        const int c = __float2int_rn(v[j].z);
        const int d = __float2int_rn(v[j].w);
        xi[j] = make_int4(a, b, c, d);
        sum += a + b + c + d;
        sumsq += (long long)a * a + (long long)b * b
               + (long long)c * c + (long long)d * d;
    }

    // Warp butterfly reduction -> every lane holds row totals
    #pragma unroll
    for (int o = 16; o > 0; o >>= 1) {
        sum   += __shfl_xor_sync(0xffffffffu, sum, o);
        sumsq += __shfl_xor_sync(0xffffffffu, sumsq, o);
    }

    // Fixed-point mean: (sum * 64) >> 16, arithmetic shift
    const int mean = (sum * 64) >> 16;
    // Exact centered sum of squares
    const long long ssy = sumsq - 2LL * (long long)mean * (long long)sum
                        + (long long)DIM * (long long)mean * (long long)mean;
    long long var = (ssy * 64) >> 16;
    if (var < 1) var = 1;

    // k = floor(log2(var)) via MSB position (exact for integers)
    const int k = 63 - __clzll((unsigned long long)var);
    const int parity = k & 1;
    const int sa = k - 4;
    const int mant = (sa >= 0) ? (int)((var >> sa) & 15)
                               : (int)((var << (-sa)) & 15);
    const int inv = s_lut[(parity << 4) | mant];
    const int ts = (k >> 1) + 15;   // p + SHIFT(0) + Q_LUT(15)

    #pragma unroll
    for (int j = 0; j < 8; j++) {
        const int col = j * 128 + lane * 4;
        float4 o;
        long long t;
        t = (((long long)((xi[j].x - mean) * inv) * (long long)s_w[col + 0]) >> ts) + s_b[col + 0];
        o.x = (float)t * 0.00390625f;
        t = (((long long)((xi[j].y - mean) * inv) * (long long)s_w[col + 1]) >> ts) + s_b[col + 1];
        o.y = (float)t * 0.00390625f;
        t = (((long long)((xi[j].z - mean) * inv) * (long long)s_w[col + 2]) >> ts) + s_b[col + 2];
        o.z = (float)t * 0.00390625f;
        t = (((long long)((xi[j].w - mean) * inv) * (long long)s_w[col + 3]) >> ts) + s_b[col + 3];
        o.w = (float)t * 0.00390625f;
        orow[j * 32 + lane] = o;
    }
}

extern "C" void kernel_launch(void* const* d_in, const int* in_sizes, int n_in,
                              void* d_out, int out_size) {
    const float* x      = (const float*)d_in[0];
    const float* weight = (const float*)d_in[1];
    const float* bias   = (const float*)d_in[2];
    // d_in[3] (isqrt_lut) intentionally unused: LUT is recomputed exactly in-kernel.
    float* out = (float*)d_out;

    const int n_rows = in_sizes[0] / DIM;
    const int blocks = (n_rows + ROWS_PER_BLOCK - 1) / ROWS_PER_BLOCK;
    iln_kernel<<<blocks, NTHREADS>>>(x, weight, bias, out, n_rows);
}